// round 4
// baseline (speedup 1.0000x reference)
#include <cuda_runtime.h>
#include <math.h>
#include <stdint.h>

#define B_   16
#define CIN_ 512
#define COUT_ 512
#define HIN_ 32
#define WIN_ 32
#define HOUT_ 64
#define WOUT_ 64

// ---------------- device scratch (static __device__ globals: allowed) -------------
__device__ float g_s1[B_ * CIN_];
__device__ float g_s2[B_ * COUT_];
__device__ float g_sr[B_ * COUT_];
__device__ float g_d[2][B_ * COUT_];
__device__ float g_A[2][CIN_ * COUT_];
__device__ float g_wr3[3 * COUT_];
__device__ float g_ydc[(size_t)B_ * HOUT_ * WOUT_ * COUT_]; // deconv out (pre-blur)
__device__ float g_x1[(size_t)B_ * HOUT_ * WOUT_ * COUT_];  // style block 1 out

static __constant__ float kFclScale = 0.04419417382415922f;   // 1/sqrt(512)
static __constant__ float kWs9      = 0.014731391274719738f;  // 1/sqrt(4608)

// ---------------- small kernels ---------------------------------------------------

// s = w @ (fw * 1/sqrt(512)) + fb   -> sout[b*512 + c]
__global__ void fcl_kernel(const float* __restrict__ w, const float* __restrict__ fw,
                           const float* __restrict__ fb, float* __restrict__ sout) {
    __shared__ float wsh[512];
    int b = blockIdx.x, c = threadIdx.x;
    wsh[c] = w[b * 512 + c];
    __syncthreads();
    float acc = 0.f;
#pragma unroll 8
    for (int k = 0; k < 512; ++k) acc += wsh[k] * fw[k * 512 + c];
    sout[b * 512 + c] = acc * kFclScale + fb[c];
}

// A[sel][cin][cout] = wscale^2 * sum_t w[t,cin,cout]^2
__global__ void a_kernel(const float* __restrict__ w1, const float* __restrict__ w2) {
    int cin = blockIdx.x, sel = blockIdx.y, c = threadIdx.x;
    const float* w = sel ? w2 : w1;
    float acc = 0.f;
#pragma unroll
    for (int t = 0; t < 9; ++t) {
        float v = w[((size_t)t * 512 + cin) * 512 + c];
        acc += v * v;
    }
    g_A[sel][cin * 512 + c] = acc * (1.0f / 4608.0f);
}

// d[sel][b][cout] = rsqrt( sum_cin A[cin][cout]*s^2 + 1e-8 )
__global__ void d_kernel() {
    __shared__ float ssq[512];
    int b = blockIdx.x, sel = blockIdx.y, c = threadIdx.x;
    const float* s = sel ? g_s2 : g_s1;
    float sv = s[b * 512 + c];
    ssq[c] = sv * sv;
    __syncthreads();
    float acc = 0.f;
#pragma unroll 8
    for (int k = 0; k < 512; ++k) acc += g_A[sel][k * 512 + c] * ssq[k];
    g_d[sel][b * 512 + c] = rsqrtf(acc + 1e-8f);
}

// wr3[j][c] = convr_w[c][j] / sqrt(512)
__global__ void wr3_kernel(const float* __restrict__ wr) {
    int c = threadIdx.x;
#pragma unroll
    for (int j = 0; j < 3; ++j) g_wr3[j * 512 + c] = wr[c * 3 + j] * kFclScale;
}

// ---------------- tiled implicit-GEMM conv ---------------------------------------
// out[b, a*ymul+yadd, p*xmul+xadd, cout0..+256) +=
//   sum over taps t, cin:  xin[b, a+dy, p+dx, cin]*s[b,cin] * wt[wi][cin][cout]*wscale
// Fused epilogue if dvec != null: v = acc*d + snoise*noise + bias; lrelu.
struct TapList { int n; int dy[9]; int dx[9]; int wi[9]; };

template <int TM>
__global__ __launch_bounds__(TM * 4)
void conv_mod_kernel(const float* __restrict__ xin, int Hin, int Win,
                     const float* __restrict__ wt, float wscale,
                     const float* __restrict__ svec, TapList taps, int Hrows,
                     int ymul, int yadd, int xmul, int xadd,
                     float* __restrict__ out,
                     const float* __restrict__ dvec, const float* __restrict__ noise,
                     const float* __restrict__ snoise, const float* __restrict__ bias) {
    constexpr int NT = TM * 4;
    constexpr int KC = 16;
    constexpr int TN = 256;
    constexpr int CSTR = NT / 64;
    __shared__ float xs[KC][TM];
    __shared__ float ws[KC][TN];

    const int tid = threadIdx.x;
    const int b = blockIdx.y / Hrows;
    const int a = blockIdx.y % Hrows;
    const int cout0 = blockIdx.x * TN;

    const int pr = tid % (TM / 8);
    const int jr = tid / (TM / 8);
    const int p0 = pr * 8, j0 = jr * 8;

    const int lpx = tid % TM;
    const int lc0 = (tid / TM) * 4;

    const int jw = (tid & 63) * 4;
    const int cw = tid >> 6;

    float acc[8][8];
#pragma unroll
    for (int i = 0; i < 8; ++i)
#pragma unroll
        for (int j = 0; j < 8; ++j) acc[i][j] = 0.f;

    const float* sb = svec + b * CIN_;

    for (int t = 0; t < taps.n; ++t) {
        const int dy = taps.dy[t], dx = taps.dx[t];
        const int iy = a + dy;
        const int ix = lpx + dx;
        const bool ok = (iy >= 0) && (iy < Hin) && (ix >= 0) && (ix < Win);
        const float* xptr = ok ? (xin + (((size_t)(b * Hin + iy)) * Win + ix) * CIN_ + lc0)
                               : xin;
        const float* wpl = wt + (size_t)taps.wi[t] * CIN_ * COUT_;

        for (int ck = 0; ck < CIN_; ck += KC) {
            __syncthreads();
            // fill xs (modulated, shifted, zero-padded)
            {
                float4 v = make_float4(0.f, 0.f, 0.f, 0.f);
                if (ok) {
                    v = *(const float4*)(xptr + ck);
                    float4 sm = *(const float4*)(sb + ck + lc0);
                    v.x *= sm.x; v.y *= sm.y; v.z *= sm.z; v.w *= sm.w;
                }
                xs[lc0 + 0][lpx] = v.x; xs[lc0 + 1][lpx] = v.y;
                xs[lc0 + 2][lpx] = v.z; xs[lc0 + 3][lpx] = v.w;
            }
            // fill ws (scaled)
#pragma unroll
            for (int i = 0; i < KC / CSTR; ++i) {
                int c = cw + i * CSTR;
                float4 wv = *(const float4*)(wpl + (size_t)(ck + c) * COUT_ + cout0 + jw);
                wv.x *= wscale; wv.y *= wscale; wv.z *= wscale; wv.w *= wscale;
                *(float4*)&ws[c][jw] = wv;
            }
            __syncthreads();

#pragma unroll
            for (int c = 0; c < KC; ++c) {
                float xv[8], wv[8];
                *(float4*)&xv[0] = *(const float4*)&xs[c][p0];
                *(float4*)&xv[4] = *(const float4*)&xs[c][p0 + 4];
                *(float4*)&wv[0] = *(const float4*)&ws[c][j0];
                *(float4*)&wv[4] = *(const float4*)&ws[c][j0 + 4];
#pragma unroll
                for (int i = 0; i < 8; ++i)
#pragma unroll
                    for (int j = 0; j < 8; ++j) acc[i][j] += xv[i] * wv[j];
            }
        }
    }

    const int oy = a * ymul + yadd;
    if (dvec) {
        float dv[8], sn[8], bi[8];
#pragma unroll
        for (int j = 0; j < 8; ++j) {
            int co = cout0 + j0 + j;
            dv[j] = dvec[b * COUT_ + co];
            sn[j] = snoise[co];
            bi[j] = bias[co];
        }
#pragma unroll
        for (int i = 0; i < 8; ++i) {
            int ox = (p0 + i) * xmul + xadd;
            float nz = noise[((size_t)b * HOUT_ + oy) * WOUT_ + ox];
            float* optr = out + (((size_t)b * HOUT_ + oy) * WOUT_ + ox) * COUT_ + cout0 + j0;
            float o[8];
#pragma unroll
            for (int j = 0; j < 8; ++j) {
                float v = acc[i][j] * dv[j] + sn[j] * nz + bi[j];
                o[j] = v >= 0.f ? v : 0.2f * v;
            }
            *(float4*)optr = *(float4*)&o[0];
            *(float4*)(optr + 4) = *(float4*)&o[4];
        }
    } else {
#pragma unroll
        for (int i = 0; i < 8; ++i) {
            int ox = (p0 + i) * xmul + xadd;
            float* optr = out + (((size_t)b * HOUT_ + oy) * WOUT_ + ox) * COUT_ + cout0 + j0;
            *(float4*)optr = *(float4*)&acc[i][0];
            *(float4*)(optr + 4) = *(float4*)&acc[i][4];
        }
    }
}

// ---------------- blur (4x4 separable) + demod + noise + bias + lrelu -------------
// f = [1,3,3,1]/8, gain 4 folded: fh = fv = [0.25, 0.75, 0.75, 0.25]
__global__ void blur_kernel(const float* __restrict__ ydc, float* __restrict__ x1out,
                            const float* __restrict__ noise, const float* __restrict__ snoise,
                            const float* __restrict__ bias) {
    const int cg = threadIdx.x & 127;
    const int c = cg * 4;
    const int xi = (blockIdx.x % 32) * 2 + (threadIdx.x >> 7);
    const int b = blockIdx.x / 32;

    const float F[4] = {0.25f, 0.75f, 0.75f, 0.25f};

    float4 dvv = *(const float4*)(&g_d[0][b * 512 + c]);
    float4 snv = *(const float4*)(snoise + c);
    float4 biv = *(const float4*)(bias + c);

    auto hrow = [&](int v) -> float4 {
        float4 r = make_float4(0.f, 0.f, 0.f, 0.f);
        if (v < 0 || v >= 64) return r;
        const float* base = ydc + (((size_t)b * 64 + v) * 64) * 512 + c;
#pragma unroll
        for (int u = 0; u < 4; ++u) {
            int xx = xi + u - 1;
            if (xx >= 0 && xx < 64) {
                float4 t = *(const float4*)(base + (size_t)xx * 512);
                float fw = F[u];
                r.x += fw * t.x; r.y += fw * t.y; r.z += fw * t.z; r.w += fw * t.w;
            }
        }
        return r;
    };

    float4 h0 = make_float4(0.f, 0.f, 0.f, 0.f);
    float4 h1 = hrow(0);
    float4 h2 = hrow(1);
    for (int y = 0; y < 64; ++y) {
        float4 h3 = hrow(y + 2);
        float4 o;
        o.x = 0.25f * h0.x + 0.75f * h1.x + 0.75f * h2.x + 0.25f * h3.x;
        o.y = 0.25f * h0.y + 0.75f * h1.y + 0.75f * h2.y + 0.25f * h3.y;
        o.z = 0.25f * h0.z + 0.75f * h1.z + 0.75f * h2.z + 0.25f * h3.z;
        o.w = 0.25f * h0.w + 0.75f * h1.w + 0.75f * h2.w + 0.25f * h3.w;
        float nz = noise[((size_t)b * 64 + y) * 64 + xi];
        float4 v;
        v.x = o.x * dvv.x + snv.x * nz + biv.x;
        v.y = o.y * dvv.y + snv.y * nz + biv.y;
        v.z = o.z * dvv.z + snv.z * nz + biv.z;
        v.w = o.w * dvv.w + snv.w * nz + biv.w;
        v.x = v.x >= 0.f ? v.x : 0.2f * v.x;
        v.y = v.y >= 0.f ? v.y : 0.2f * v.y;
        v.z = v.z >= 0.f ? v.z : 0.2f * v.z;
        v.w = v.w >= 0.f ? v.w : 0.2f * v.w;
        *(float4*)(x1out + (((size_t)b * 64 + y) * 64 + xi) * 512 + c) = v;
        h0 = h1; h1 = h2; h2 = h3;
    }
}

// ---------------- toRGB: 1x1 modulated conv (no demod) + bias + lrelu -------------
__global__ void torgb_kernel(const float* __restrict__ x2, float* __restrict__ rgb,
                             const float* __restrict__ biasr) {
    const int warp = threadIdx.x >> 5, lane = threadIdx.x & 31;
    const int pix = blockIdx.x * 8 + warp;   // [0, 16*4096)
    const int b = pix >> 12;
    const float* xp = x2 + (size_t)pix * 512;
    const float* sp = g_sr + b * 512;
    float r0 = 0.f, r1 = 0.f, r2 = 0.f;
#pragma unroll
    for (int k = 0; k < 4; ++k) {
        int c = lane * 4 + k * 128;
        float4 xv = *(const float4*)(xp + c);
        float4 sv = *(const float4*)(sp + c);
        xv.x *= sv.x; xv.y *= sv.y; xv.z *= sv.z; xv.w *= sv.w;
        float4 w0 = *(const float4*)(g_wr3 + 0 * 512 + c);
        float4 w1 = *(const float4*)(g_wr3 + 1 * 512 + c);
        float4 w2 = *(const float4*)(g_wr3 + 2 * 512 + c);
        r0 += xv.x * w0.x + xv.y * w0.y + xv.z * w0.z + xv.w * w0.w;
        r1 += xv.x * w1.x + xv.y * w1.y + xv.z * w1.z + xv.w * w1.w;
        r2 += xv.x * w2.x + xv.y * w2.y + xv.z * w2.z + xv.w * w2.w;
    }
#pragma unroll
    for (int off = 16; off > 0; off >>= 1) {
        r0 += __shfl_xor_sync(0xffffffffu, r0, off);
        r1 += __shfl_xor_sync(0xffffffffu, r1, off);
        r2 += __shfl_xor_sync(0xffffffffu, r2, off);
    }
    if (lane == 0) {
        float v0 = r0 + biasr[0];
        float v1 = r1 + biasr[1];
        float v2 = r2 + biasr[2];
        rgb[(size_t)pix * 3 + 0] = v0 >= 0.f ? v0 : 0.2f * v0;
        rgb[(size_t)pix * 3 + 1] = v1 >= 0.f ? v1 : 0.2f * v1;
        rgb[(size_t)pix * 3 + 2] = v2 >= 0.f ? v2 : 0.2f * v2;
    }
}

// ---------------- launch ----------------------------------------------------------
extern "C" void kernel_launch(void* const* d_in, const int* in_sizes, int n_in,
                              void* d_out, int out_size) {
    const float* x       = (const float*)d_in[0];
    const float* w       = (const float*)d_in[1];
    const float* noise1  = (const float*)d_in[2];
    const float* noise2  = (const float*)d_in[3];
    const float* fcl1_w  = (const float*)d_in[4];
    const float* fcl1_b  = (const float*)d_in[5];
    const float* conv1_w = (const float*)d_in[6];
    const float* sn1     = (const float*)d_in[7];
    const float* bias1   = (const float*)d_in[8];
    const float* fcl2_w  = (const float*)d_in[9];
    const float* fcl2_b  = (const float*)d_in[10];
    const float* conv2_w = (const float*)d_in[11];
    const float* sn2     = (const float*)d_in[12];
    const float* bias2   = (const float*)d_in[13];
    const float* fclr_w  = (const float*)d_in[14];
    const float* fclr_b  = (const float*)d_in[15];
    const float* convr_w = (const float*)d_in[16];
    const float* biasr   = (const float*)d_in[17];

    float* x2out  = (float*)d_out;
    float* rgbout = x2out + (size_t)B_ * HOUT_ * WOUT_ * COUT_;

    float *s1, *s2, *sr, *dd, *ydc, *x1;
    cudaGetSymbolAddress((void**)&s1, g_s1);
    cudaGetSymbolAddress((void**)&s2, g_s2);
    cudaGetSymbolAddress((void**)&sr, g_sr);
    cudaGetSymbolAddress((void**)&dd, g_d);
    cudaGetSymbolAddress((void**)&ydc, g_ydc);
    cudaGetSymbolAddress((void**)&x1, g_x1);
    float* d1 = dd;               // g_d[0]
    float* d2 = dd + B_ * COUT_;  // g_d[1]

    // styles + demod + toRGB weight prep
    fcl_kernel<<<B_, 512>>>(w, fcl1_w, fcl1_b, s1);
    fcl_kernel<<<B_, 512>>>(w, fcl2_w, fcl2_b, s2);
    fcl_kernel<<<B_, 512>>>(w, fclr_w, fclr_b, sr);
    a_kernel<<<dim3(512, 2), 512>>>(conv1_w, conv2_w);
    d_kernel<<<dim3(B_, 2), 512>>>();
    wr3_kernel<<<1, 512>>>(convr_w);

    const float WS9 = 0.014731391274719738f; // 1/sqrt(4608)

    // deconv (conv_transpose stride 2, SAME => pad (2,1)): 4 parity classes.
    // even out-row: taps kh={0,2} at ih={a-1,a}; odd: kh=1 at ih=a. Same for cols.
    for (int rh = 0; rh < 2; ++rh) {
        for (int rw = 0; rw < 2; ++rw) {
            TapList tl;
            int n = 0;
            const int khs0[2] = {0, 2};
            int nkh = rh ? 1 : 2;
            int nkw = rw ? 1 : 2;
            for (int ih = 0; ih < nkh; ++ih) {
                int kh = rh ? 1 : khs0[ih];
                int dy = (kh == 0) ? -1 : 0;
                for (int iw = 0; iw < nkw; ++iw) {
                    int kw = rw ? 1 : khs0[iw];
                    int dx = (kw == 0) ? -1 : 0;
                    tl.dy[n] = dy; tl.dx[n] = dx; tl.wi[n] = kh * 3 + kw; ++n;
                }
            }
            tl.n = n;
            conv_mod_kernel<32><<<dim3(2, B_ * 32), 128>>>(
                x, HIN_, WIN_, conv1_w, WS9, s1, tl, 32,
                2, rh, 2, rw, ydc, nullptr, nullptr, nullptr, nullptr);
        }
    }

    // blur + demod1 + noise1 + bias1 + lrelu -> g_x1
    blur_kernel<<<B_ * 32, 256>>>(ydc, x1, noise1, sn1, bias1);

    // conv2 (3x3 SAME) fused epilogue -> x2 (d_out)
    {
        TapList tl;
        tl.n = 9;
        for (int kh = 0; kh < 3; ++kh)
            for (int kw = 0; kw < 3; ++kw) {
                int t = kh * 3 + kw;
                tl.dy[t] = kh - 1; tl.dx[t] = kw - 1; tl.wi[t] = t;
            }
        conv_mod_kernel<64><<<dim3(2, B_ * 64), 256>>>(
            x1, HOUT_, WOUT_, conv2_w, WS9, s2, tl, 64,
            1, 0, 1, 0, x2out, d2, noise2, sn2, bias2);
    }

    // toRGB -> rgb (d_out tail)
    torgb_kernel<<<(B_ * HOUT_ * WOUT_) / 8, 256>>>(x2out, rgbout, biasr);
}

// round 8
// speedup vs baseline: 3.3051x; 3.3051x over previous
#include <cuda_runtime.h>
#include <cuda_fp16.h>
#include <math.h>
#include <stdint.h>

#define B_   16
#define HIN_ 32
#define WIN_ 32

// ---- base-PTX helpers (sm_80-level: compile at compute_103) ----
__device__ __forceinline__ uint32_t smem_u32(const void* p) {
    uint32_t a;
    asm("{ .reg .u64 t; cvta.to.shared.u64 t, %1; cvt.u32.u64 %0, t; }" : "=r"(a) : "l"(p));
    return a;
}
#define LDSM4(r0, r1, r2, r3, addr) \
    asm volatile("ldmatrix.sync.aligned.m8n8.x4.shared.b16 {%0,%1,%2,%3}, [%4];" \
        : "=r"(r0), "=r"(r1), "=r"(r2), "=r"(r3) : "r"(addr))
__device__ __forceinline__ void mma16816(float* c, const uint32_t* a, const uint32_t* b) {
    asm volatile("mma.sync.aligned.m16n8k16.row.col.f32.f16.f16.f32 "
                 "{%0,%1,%2,%3}, {%4,%5,%6,%7}, {%8,%9}, {%0,%1,%2,%3};"
                 : "+f"(c[0]), "+f"(c[1]), "+f"(c[2]), "+f"(c[3])
                 : "r"(a[0]), "r"(a[1]), "r"(a[2]), "r"(a[3]), "r"(b[0]), "r"(b[1]));
}
__device__ __forceinline__ void cpa16(uint32_t dst, const void* src, uint32_t sz) {
    asm volatile("cp.async.cg.shared.global [%0], [%1], 16, %2;" :: "r"(dst), "l"(src), "r"(sz));
}
#define CP_COMMIT() asm volatile("cp.async.commit_group;")
#define CP_WAIT0()  asm volatile("cp.async.wait_group 0;")
#define CP_WAIT1()  asm volatile("cp.async.wait_group 1;")
#define CP_WAIT2()  asm volatile("cp.async.wait_group 2;")

// ---- scratch ----
__device__ float g_s1[B_ * 512];
__device__ float g_s2[B_ * 512];
__device__ float g_sr[B_ * 512];
__device__ float g_d[2][B_ * 512];
__device__ float g_A[2][512 * 512];
__device__ float g_wr3[3 * 512];
__device__ float g_ydc[(size_t)B_ * 64 * 64 * 512];
__device__ __half g_a1[(size_t)B_ * 32 * 32 * 512];   // x*s1*wscale, fp16
__device__ __half g_a2[(size_t)B_ * 64 * 64 * 512];   // block1 out *s2*wscale, fp16
__device__ __half g_wh[(size_t)2 * 9 * 512 * 512];    // wT[conv][t][cout][cin] hi
__device__ __half g_wl[(size_t)2 * 9 * 512 * 512];    // lo

static __constant__ float kFclScale = 0.04419417382415922f;   // 1/sqrt(512)
#define WS9F 0.014731391274719738f                            // 1/sqrt(4608)

// ---- small kernels ----
__global__ void fcl_kernel(const float* __restrict__ w, const float* __restrict__ fw,
                           const float* __restrict__ fb, float* __restrict__ sout) {
    __shared__ float wsh[512];
    int b = blockIdx.x, c = threadIdx.x;
    wsh[c] = w[b * 512 + c];
    __syncthreads();
    float acc = 0.f;
#pragma unroll 8
    for (int k = 0; k < 512; ++k) acc += wsh[k] * fw[k * 512 + c];
    sout[b * 512 + c] = acc * kFclScale + fb[c];
}

__global__ void a_kernel(const float* __restrict__ w1, const float* __restrict__ w2) {
    int cin = blockIdx.x, sel = blockIdx.y, c = threadIdx.x;
    const float* w = sel ? w2 : w1;
    float acc = 0.f;
#pragma unroll
    for (int t = 0; t < 9; ++t) {
        float v = w[((size_t)t * 512 + cin) * 512 + c];
        acc += v * v;
    }
    g_A[sel][cin * 512 + c] = acc * (1.0f / 4608.0f);
}

__global__ void d_kernel() {
    __shared__ float ssq[512];
    int b = blockIdx.x, sel = blockIdx.y, c = threadIdx.x;
    const float* s = sel ? g_s2 : g_s1;
    float sv = s[b * 512 + c];
    ssq[c] = sv * sv;
    __syncthreads();
    float acc = 0.f;
#pragma unroll 8
    for (int k = 0; k < 512; ++k) acc += g_A[sel][k * 512 + c] * ssq[k];
    g_d[sel][b * 512 + c] = rsqrtf(acc + 1e-8f);
}

__global__ void wr3_kernel(const float* __restrict__ wr) {
    int c = threadIdx.x;
#pragma unroll
    for (int j = 0; j < 3; ++j) g_wr3[j * 512 + c] = wr[c * 3 + j] * kFclScale;
}

// A1 = fp16(x * s1 * wscale)
__global__ void prep_a1(const float* __restrict__ x) {
    int idx = blockIdx.x * 256 + threadIdx.x;  // float4 units
    float4 v = ((const float4*)x)[idx];
    int b = idx >> 17, c4 = idx & 127;
    float4 s = ((const float4*)g_s1)[b * 128 + c4];
    __half2 h0 = __floats2half2_rn(v.x * s.x * WS9F, v.y * s.y * WS9F);
    __half2 h1 = __floats2half2_rn(v.z * s.z * WS9F, v.w * s.w * WS9F);
    ((__half2*)g_a1)[idx * 2] = h0;
    ((__half2*)g_a1)[idx * 2 + 1] = h1;
}

// wT[conv][t][cout][cin] = transpose(conv_w[t]), fp16 hi/lo (no scale)
__global__ void wsplit_kernel(const float* __restrict__ w1, const float* __restrict__ w2) {
    __shared__ float tile[32][33];
    int tz = blockIdx.z, conv = tz / 9, t = tz % 9;
    const float* w = conv ? w2 : w1;
    __half* dh = g_wh + (size_t)conv * 9 * 512 * 512;
    __half* dl = g_wl + (size_t)conv * 9 * 512 * 512;
    int ci0 = blockIdx.x * 32, co0 = blockIdx.y * 32;
    int tx = threadIdx.x & 31, ty = threadIdx.x >> 5;
#pragma unroll
    for (int r = 0; r < 4; ++r)
        tile[ty + r * 8][tx] = w[(((size_t)t * 512 + ci0 + ty + r * 8) << 9) + co0 + tx];
    __syncthreads();
#pragma unroll
    for (int r = 0; r < 4; ++r) {
        int co = co0 + ty + r * 8;
        float v = tile[tx][ty + r * 8];
        __half h = __float2half_rn(v);
        size_t off = (((size_t)t * 512 + co) << 9) + ci0 + tx;
        dh[off] = h;
        dl[off] = __float2half_rn(v - __half2float(h));
    }
}

// ---- HMMA implicit-GEMM conv: CTA 128px x 128cout, 8 warps (4M x 2N), K-stage 64 ----
struct TapList { int n; int dy[9]; int dx[9]; int wi[9]; };
#define ASTAGE 18432         // 128 rows * 144B
#define STAGE  55296         // A (18432) + B 256 rows * 144B (36864)
#define SMEMSZ (3 * STAGE)   // 165888

__global__ __launch_bounds__(256)
void mma_conv_kernel(const __half* __restrict__ xin, int Hin, int Win,
                     const __half* __restrict__ wh, const __half* __restrict__ wl,
                     TapList taps, int tilesPerImg, int pxs, int pxm,
                     int ymul, int yadd, int xmul, int xadd,
                     float* __restrict__ out,
                     const float* __restrict__ dvec, const float* __restrict__ noise,
                     const float* __restrict__ snoise, const float* __restrict__ bias) {
    extern __shared__ __align__(16) char smem[];
    const uint32_t su = smem_u32(smem);
    const int tid = threadIdx.x, lane = tid & 31, wid = tid >> 5;
    const int b = blockIdx.y / tilesPerImg;
    const int a0 = (blockIdx.y % tilesPerImg) * (128 >> pxs);
    const int cout0 = blockIdx.x * 128;
    const int m0 = (wid & 3) * 32, n0 = (wid >> 2) * 64;

    float acc[2][8][4];
#pragma unroll
    for (int i = 0; i < 2; ++i)
#pragma unroll
        for (int j = 0; j < 8; ++j)
#pragma unroll
            for (int k = 0; k < 4; ++k) acc[i][j][k] = 0.f;

    const int S = taps.n * 8;

    auto load_stage = [&](int st, int p) {
        int t = st >> 3, ck = (st & 7) << 6;
        uint32_t base = su + p * STAGE;
        int dy = taps.dy[t], dx = taps.dx[t];
#pragma unroll
        for (int i = 0; i < 4; ++i) {   // A: 128 rows x 64 fp16
            int id = tid + i * 256;
            int r = id >> 3, seg = id & 7;
            int iy = a0 + (r >> pxs) + dy, ix = (r & pxm) + dx;
            bool ok = ((unsigned)iy < (unsigned)Hin) && ((unsigned)ix < (unsigned)Win);
            const void* src = xin + ((((size_t)b * Hin + (ok ? iy : 0)) * Win + (ok ? ix : 0)) << 9)
                              + ck + (seg << 3);
            cpa16(base + r * 144 + seg * 16, src, ok ? 16u : 0u);
        }
        const __half* wth = wh + (((size_t)(taps.wi[t] * 512 + cout0)) << 9) + ck;
        const __half* wtl = wl + (((size_t)(taps.wi[t] * 512 + cout0)) << 9) + ck;
#pragma unroll
        for (int i = 0; i < 8; ++i) {   // B: rows 0-127 hi, 128-255 lo
            int id = tid + i * 256;
            int row = id >> 3, seg = id & 7;
            const __half* src = (row < 128 ? wth + ((size_t)row << 9)
                                           : wtl + ((size_t)(row - 128) << 9)) + (seg << 3);
            cpa16(base + ASTAGE + row * 144 + seg * 16, src, 16u);
        }
    };

    auto compute = [&](int p) {
        uint32_t Ab = su + p * STAGE;
        uint32_t Bb = Ab + ASTAGE;
#pragma unroll
        for (int kk = 0; kk < 64; kk += 16) {
            uint32_t a[2][4];
#pragma unroll
            for (int mi = 0; mi < 2; ++mi) {
                uint32_t addr = Ab + (m0 + mi * 16 + (lane & 15)) * 144
                                + (kk + ((lane >> 4) << 3)) * 2;
                LDSM4(a[mi][0], a[mi][1], a[mi][2], a[mi][3], addr);
            }
            uint32_t bb[2][8][2];
#pragma unroll
            for (int hl = 0; hl < 2; ++hl)
#pragma unroll
                for (int ng = 0; ng < 4; ++ng) {
                    int row = hl * 128 + n0 + ng * 16 + (lane & 7) + ((lane >> 4) << 3);
                    uint32_t addr = Bb + row * 144 + (kk + (((lane >> 3) & 1) << 3)) * 2;
                    uint32_t r0, r1, r2, r3;
                    LDSM4(r0, r1, r2, r3, addr);
                    bb[hl][ng * 2][0] = r0;     bb[hl][ng * 2][1] = r1;
                    bb[hl][ng * 2 + 1][0] = r2; bb[hl][ng * 2 + 1][1] = r3;
                }
#pragma unroll
            for (int mi = 0; mi < 2; ++mi)
#pragma unroll
                for (int ni = 0; ni < 8; ++ni) {
                    mma16816(acc[mi][ni], a[mi], bb[0][ni]);
                    mma16816(acc[mi][ni], a[mi], bb[1][ni]);
                }
        }
    };

    load_stage(0, 0); CP_COMMIT();
    load_stage(1, 1); CP_COMMIT();
    for (int st = 0; st < S; ++st) {
        int nxt = st + 2;
        if (nxt < S) { load_stage(nxt, nxt % 3); CP_COMMIT(); CP_WAIT2(); }
        else if (st + 1 < S) { CP_WAIT1(); }
        else { CP_WAIT0(); }
        __syncthreads();
        compute(st % 3);
        __syncthreads();
    }

    // epilogue
    const int quad = lane >> 2, tq = lane & 3;
    if (dvec) {
        float2 dv2[8], sn2[8], bi2[8];
#pragma unroll
        for (int ni = 0; ni < 8; ++ni) {
            int col = cout0 + n0 + ni * 8 + tq * 2;
            dv2[ni] = *(const float2*)(dvec + b * 512 + col);
            sn2[ni] = *(const float2*)(snoise + col);
            bi2[ni] = *(const float2*)(bias + col);
        }
#pragma unroll
        for (int mi = 0; mi < 2; ++mi)
#pragma unroll
            for (int h = 0; h < 2; ++h) {
                int r = m0 + mi * 16 + quad + h * 8;
                int oy = (a0 + (r >> pxs)) * ymul + yadd;
                int ox = (r & pxm) * xmul + xadd;
                size_t pbase = (((size_t)b * 64 + oy) * 64 + ox) << 9;
                float nz = noise[(((size_t)b * 64 + oy) << 6) + ox];
#pragma unroll
                for (int ni = 0; ni < 8; ++ni) {
                    float c0 = acc[mi][ni][h * 2], c1 = acc[mi][ni][h * 2 + 1];
                    float2 v;
                    v.x = c0 * dv2[ni].x + sn2[ni].x * nz + bi2[ni].x;
                    v.y = c1 * dv2[ni].y + sn2[ni].y * nz + bi2[ni].y;
                    v.x = v.x >= 0.f ? v.x : 0.2f * v.x;
                    v.y = v.y >= 0.f ? v.y : 0.2f * v.y;
                    *(float2*)(out + pbase + cout0 + n0 + ni * 8 + tq * 2) = v;
                }
            }
    } else {
#pragma unroll
        for (int mi = 0; mi < 2; ++mi)
#pragma unroll
            for (int h = 0; h < 2; ++h) {
                int r = m0 + mi * 16 + quad + h * 8;
                int oy = (a0 + (r >> pxs)) * ymul + yadd;
                int ox = (r & pxm) * xmul + xadd;
                size_t pbase = (((size_t)b * 64 + oy) * 64 + ox) << 9;
#pragma unroll
                for (int ni = 0; ni < 8; ++ni) {
                    float2 v = make_float2(acc[mi][ni][h * 2], acc[mi][ni][h * 2 + 1]);
                    *(float2*)(out + pbase + cout0 + n0 + ni * 8 + tq * 2) = v;
                }
            }
    }
}

// ---- blur + demod1 + noise + bias + lrelu -> fp16 (v*s2*wscale) ----
__global__ void blur_kernel(const float* __restrict__ ydc, __half* __restrict__ xout,
                            const float* __restrict__ noise, const float* __restrict__ snoise,
                            const float* __restrict__ bias) {
    const int cg = threadIdx.x & 127, c = cg * 4;
    const int xi = (blockIdx.x % 32) * 2 + (threadIdx.x >> 7);
    const int b = blockIdx.x / 32;
    const float F[4] = {0.25f, 0.75f, 0.75f, 0.25f};

    float4 dvv = *(const float4*)(&g_d[0][b * 512 + c]);
    float4 snv = *(const float4*)(snoise + c);
    float4 biv = *(const float4*)(bias + c);
    float4 s2v = *(const float4*)(&g_s2[b * 512 + c]);

    auto hrow = [&](int v) -> float4 {
        float4 r = make_float4(0.f, 0.f, 0.f, 0.f);
        if (v < 0 || v >= 64) return r;
        const float* base = ydc + (((size_t)b * 64 + v) * 64) * 512 + c;
#pragma unroll
        for (int u = 0; u < 4; ++u) {
            int xx = xi + u - 1;
            if (xx >= 0 && xx < 64) {
                float4 t = *(const float4*)(base + (size_t)xx * 512);
                r.x += F[u] * t.x; r.y += F[u] * t.y; r.z += F[u] * t.z; r.w += F[u] * t.w;
            }
        }
        return r;
    };

    float4 h0 = make_float4(0.f, 0.f, 0.f, 0.f);
    float4 h1 = hrow(0), h2 = hrow(1);
    for (int y = 0; y < 64; ++y) {
        float4 h3 = hrow(y + 2);
        float4 o;
        o.x = 0.25f * h0.x + 0.75f * h1.x + 0.75f * h2.x + 0.25f * h3.x;
        o.y = 0.25f * h0.y + 0.75f * h1.y + 0.75f * h2.y + 0.25f * h3.y;
        o.z = 0.25f * h0.z + 0.75f * h1.z + 0.75f * h2.z + 0.25f * h3.z;
        o.w = 0.25f * h0.w + 0.75f * h1.w + 0.75f * h2.w + 0.25f * h3.w;
        float nz = noise[((size_t)b * 64 + y) * 64 + xi];
        float4 v;
        v.x = o.x * dvv.x + snv.x * nz + biv.x;
        v.y = o.y * dvv.y + snv.y * nz + biv.y;
        v.z = o.z * dvv.z + snv.z * nz + biv.z;
        v.w = o.w * dvv.w + snv.w * nz + biv.w;
        v.x = v.x >= 0.f ? v.x : 0.2f * v.x;
        v.y = v.y >= 0.f ? v.y : 0.2f * v.y;
        v.z = v.z >= 0.f ? v.z : 0.2f * v.z;
        v.w = v.w >= 0.f ? v.w : 0.2f * v.w;
        size_t off = (((size_t)b * 64 + y) * 64 + xi) * 512 + c;
        __half2 p0 = __floats2half2_rn(v.x * s2v.x * WS9F, v.y * s2v.y * WS9F);
        __half2 p1 = __floats2half2_rn(v.z * s2v.z * WS9F, v.w * s2v.w * WS9F);
        ((__half2*)(xout + off))[0] = p0;
        ((__half2*)(xout + off))[1] = p1;
        h0 = h1; h1 = h2; h2 = h3;
    }
}

// ---- toRGB ----
__global__ void torgb_kernel(const float* __restrict__ x2, float* __restrict__ rgb,
                             const float* __restrict__ biasr) {
    const int warp = threadIdx.x >> 5, lane = threadIdx.x & 31;
    const int pix = blockIdx.x * 8 + warp;
    const int b = pix >> 12;
    const float* xp = x2 + (size_t)pix * 512;
    const float* sp = g_sr + b * 512;
    float r0 = 0.f, r1 = 0.f, r2 = 0.f;
#pragma unroll
    for (int k = 0; k < 4; ++k) {
        int c = lane * 4 + k * 128;
        float4 xv = *(const float4*)(xp + c);
        float4 sv = *(const float4*)(sp + c);
        xv.x *= sv.x; xv.y *= sv.y; xv.z *= sv.z; xv.w *= sv.w;
        float4 w0 = *(const float4*)(g_wr3 + 0 * 512 + c);
        float4 w1 = *(const float4*)(g_wr3 + 1 * 512 + c);
        float4 w2 = *(const float4*)(g_wr3 + 2 * 512 + c);
        r0 += xv.x * w0.x + xv.y * w0.y + xv.z * w0.z + xv.w * w0.w;
        r1 += xv.x * w1.x + xv.y * w1.y + xv.z * w1.z + xv.w * w1.w;
        r2 += xv.x * w2.x + xv.y * w2.y + xv.z * w2.z + xv.w * w2.w;
    }
#pragma unroll
    for (int off = 16; off > 0; off >>= 1) {
        r0 += __shfl_xor_sync(0xffffffffu, r0, off);
        r1 += __shfl_xor_sync(0xffffffffu, r1, off);
        r2 += __shfl_xor_sync(0xffffffffu, r2, off);
    }
    if (lane == 0) {
        float v0 = r0 + biasr[0], v1 = r1 + biasr[1], v2 = r2 + biasr[2];
        rgb[(size_t)pix * 3 + 0] = v0 >= 0.f ? v0 : 0.2f * v0;
        rgb[(size_t)pix * 3 + 1] = v1 >= 0.f ? v1 : 0.2f * v1;
        rgb[(size_t)pix * 3 + 2] = v2 >= 0.f ? v2 : 0.2f * v2;
    }
}

// ---- launch ----
extern "C" void kernel_launch(void* const* d_in, const int* in_sizes, int n_in,
                              void* d_out, int out_size) {
    const float* x       = (const float*)d_in[0];
    const float* w       = (const float*)d_in[1];
    const float* noise1  = (const float*)d_in[2];
    const float* noise2  = (const float*)d_in[3];
    const float* fcl1_w  = (const float*)d_in[4];
    const float* fcl1_b  = (const float*)d_in[5];
    const float* conv1_w = (const float*)d_in[6];
    const float* sn1     = (const float*)d_in[7];
    const float* bias1   = (const float*)d_in[8];
    const float* fcl2_w  = (const float*)d_in[9];
    const float* fcl2_b  = (const float*)d_in[10];
    const float* conv2_w = (const float*)d_in[11];
    const float* sn2     = (const float*)d_in[12];
    const float* bias2   = (const float*)d_in[13];
    const float* fclr_w  = (const float*)d_in[14];
    const float* fclr_b  = (const float*)d_in[15];
    const float* convr_w = (const float*)d_in[16];
    const float* biasr   = (const float*)d_in[17];

    float* x2out  = (float*)d_out;
    float* rgbout = x2out + (size_t)B_ * 64 * 64 * 512;

    float *s1, *s2, *sr, *dd, *ydc;
    __half *a1, *a2, *wh, *wl;
    cudaGetSymbolAddress((void**)&s1, g_s1);
    cudaGetSymbolAddress((void**)&s2, g_s2);
    cudaGetSymbolAddress((void**)&sr, g_sr);
    cudaGetSymbolAddress((void**)&dd, g_d);
    cudaGetSymbolAddress((void**)&ydc, g_ydc);
    cudaGetSymbolAddress((void**)&a1, g_a1);
    cudaGetSymbolAddress((void**)&a2, g_a2);
    cudaGetSymbolAddress((void**)&wh, g_wh);
    cudaGetSymbolAddress((void**)&wl, g_wl);
    float* d2 = dd + B_ * 512;

    cudaFuncSetAttribute(mma_conv_kernel, cudaFuncAttributeMaxDynamicSharedMemorySize, SMEMSZ);

    fcl_kernel<<<B_, 512>>>(w, fcl1_w, fcl1_b, s1);
    fcl_kernel<<<B_, 512>>>(w, fcl2_w, fcl2_b, s2);
    fcl_kernel<<<B_, 512>>>(w, fclr_w, fclr_b, sr);
    a_kernel<<<dim3(512, 2), 512>>>(conv1_w, conv2_w);
    d_kernel<<<dim3(B_, 2), 512>>>();
    wr3_kernel<<<1, 512>>>(convr_w);
    prep_a1<<<8192, 256>>>(x);
    wsplit_kernel<<<dim3(16, 16, 18), 256>>>(conv1_w, conv2_w);

    // deconv: 4 parity classes (dense shifted GEMMs), 128-px tiles (4 rows x 32)
    for (int rh = 0; rh < 2; ++rh) {
        for (int rw = 0; rw < 2; ++rw) {
            TapList tl;
            int n = 0;
            const int khs0[2] = {0, 2};
            int nkh = rh ? 1 : 2, nkw = rw ? 1 : 2;
            for (int ih = 0; ih < nkh; ++ih) {
                int kh = rh ? 1 : khs0[ih];
                for (int iw = 0; iw < nkw; ++iw) {
                    int kw = rw ? 1 : khs0[iw];
                    tl.dy[n] = (kh == 0) ? -1 : 0;
                    tl.dx[n] = (kw == 0) ? -1 : 0;
                    tl.wi[n] = kh * 3 + kw;
                    ++n;
                }
            }
            tl.n = n;
            mma_conv_kernel<<<dim3(4, B_ * 8), 256, SMEMSZ>>>(
                a1, 32, 32, wh, wl, tl, 8, 5, 31,
                2, rh, 2, rw, ydc, nullptr, nullptr, nullptr, nullptr);
        }
    }

    blur_kernel<<<B_ * 32, 256>>>(ydc, a2, noise1, sn1, bias1);

    // conv2: 3x3 SAME, fused demod/noise/bias/lrelu -> d_out (128-px tiles: 2 rows x 64)
    {
        TapList tl;
        tl.n = 9;
        for (int kh = 0; kh < 3; ++kh)
            for (int kw = 0; kw < 3; ++kw) {
                int t = kh * 3 + kw;
                tl.dy[t] = kh - 1; tl.dx[t] = kw - 1; tl.wi[t] = t;
            }
        mma_conv_kernel<<<dim3(4, B_ * 32), 256, SMEMSZ>>>(
            a2, 64, 64, wh + (size_t)9 * 512 * 512, wl + (size_t)9 * 512 * 512, tl, 32, 6, 63,
            1, 0, 1, 0, x2out, d2, noise2, sn2, bias2);
    }

    torgb_kernel<<<(B_ * 64 * 64) / 8, 256>>>(x2out, rgbout, biasr);
}

// round 9
// speedup vs baseline: 6.0742x; 1.8378x over previous
#include <cuda_runtime.h>
#include <cuda_fp16.h>
#include <math.h>
#include <stdint.h>

#define B_   16

// ---- base-PTX helpers ----
__device__ __forceinline__ uint32_t smem_u32(const void* p) {
    uint32_t a;
    asm("{ .reg .u64 t; cvta.to.shared.u64 t, %1; cvt.u32.u64 %0, t; }" : "=r"(a) : "l"(p));
    return a;
}
#define LDSM4(r0, r1, r2, r3, addr) \
    asm volatile("ldmatrix.sync.aligned.m8n8.x4.shared.b16 {%0,%1,%2,%3}, [%4];" \
        : "=r"(r0), "=r"(r1), "=r"(r2), "=r"(r3) : "r"(addr))
__device__ __forceinline__ void mma16816(float* c, const uint32_t* a, const uint32_t* b) {
    asm volatile("mma.sync.aligned.m16n8k16.row.col.f32.f16.f16.f32 "
                 "{%0,%1,%2,%3}, {%4,%5,%6,%7}, {%8,%9}, {%0,%1,%2,%3};"
                 : "+f"(c[0]), "+f"(c[1]), "+f"(c[2]), "+f"(c[3])
                 : "r"(a[0]), "r"(a[1]), "r"(a[2]), "r"(a[3]), "r"(b[0]), "r"(b[1]));
}
__device__ __forceinline__ void cpa16(uint32_t dst, const void* src, uint32_t sz) {
    asm volatile("cp.async.cg.shared.global [%0], [%1], 16, %2;" :: "r"(dst), "l"(src), "r"(sz));
}
#define CP_COMMIT() asm volatile("cp.async.commit_group;")
#define CP_WAIT0()  asm volatile("cp.async.wait_group 0;")
#define CP_WAIT1()  asm volatile("cp.async.wait_group 1;")
#define CP_WAIT2()  asm volatile("cp.async.wait_group 2;")

// ---- scratch ----
__device__ float g_s1[B_ * 512];
__device__ float g_s2[B_ * 512];
__device__ float g_sr[B_ * 512];
__device__ float g_d[2][B_ * 512];
__device__ float g_A[2][512 * 512];
__device__ float g_wr3[3 * 512];
__device__ float g_ydc[(size_t)B_ * 64 * 64 * 512];
__device__ __half g_a1[(size_t)B_ * 32 * 32 * 512];   // x*s1*wscale, fp16
__device__ __half g_a2[(size_t)B_ * 64 * 64 * 512];   // block1 out *s2*wscale, fp16
__device__ __half g_wh[(size_t)2 * 9 * 512 * 512];    // wT[conv][t][cout][cin] fp16

static __constant__ float kFclScale = 0.04419417382415922f;   // 1/sqrt(512)
#define WS9F 0.014731391274719738f                            // 1/sqrt(4608)

// ---- small kernels ----
__global__ void fcl_kernel(const float* __restrict__ w, const float* __restrict__ fw,
                           const float* __restrict__ fb, float* __restrict__ sout) {
    __shared__ float wsh[512];
    int b = blockIdx.x, c = threadIdx.x;
    wsh[c] = w[b * 512 + c];
    __syncthreads();
    float acc = 0.f;
#pragma unroll 8
    for (int k = 0; k < 512; ++k) acc += wsh[k] * fw[k * 512 + c];
    sout[b * 512 + c] = acc * kFclScale + fb[c];
}

__global__ void a_kernel(const float* __restrict__ w1, const float* __restrict__ w2) {
    int cin = blockIdx.x, sel = blockIdx.y, c = threadIdx.x;
    const float* w = sel ? w2 : w1;
    float acc = 0.f;
#pragma unroll
    for (int t = 0; t < 9; ++t) {
        float v = w[((size_t)t * 512 + cin) * 512 + c];
        acc += v * v;
    }
    g_A[sel][cin * 512 + c] = acc * (1.0f / 4608.0f);
}

__global__ void d_kernel() {
    __shared__ float ssq[512];
    int b = blockIdx.x, sel = blockIdx.y, c = threadIdx.x;
    const float* s = sel ? g_s2 : g_s1;
    float sv = s[b * 512 + c];
    ssq[c] = sv * sv;
    __syncthreads();
    float acc = 0.f;
#pragma unroll 8
    for (int k = 0; k < 512; ++k) acc += g_A[sel][k * 512 + c] * ssq[k];
    g_d[sel][b * 512 + c] = rsqrtf(acc + 1e-8f);
}

__global__ void wr3_kernel(const float* __restrict__ wr) {
    int c = threadIdx.x;
#pragma unroll
    for (int j = 0; j < 3; ++j) g_wr3[j * 512 + c] = wr[c * 3 + j] * kFclScale;
}

// A1 = fp16(x * s1 * wscale)
__global__ void prep_a1(const float* __restrict__ x) {
    int idx = blockIdx.x * 256 + threadIdx.x;  // float4 units
    float4 v = ((const float4*)x)[idx];
    int b = idx >> 17, c4 = idx & 127;
    float4 s = ((const float4*)g_s1)[b * 128 + c4];
    __half2 h0 = __floats2half2_rn(v.x * s.x * WS9F, v.y * s.y * WS9F);
    __half2 h1 = __floats2half2_rn(v.z * s.z * WS9F, v.w * s.w * WS9F);
    ((__half2*)g_a1)[idx * 2] = h0;
    ((__half2*)g_a1)[idx * 2 + 1] = h1;
}

// wT[conv][t][cout][cin] = fp16(transpose(conv_w[t]))
__global__ void wprep_kernel(const float* __restrict__ w1, const float* __restrict__ w2) {
    __shared__ float tile[32][33];
    int tz = blockIdx.z, conv = tz / 9, t = tz % 9;
    const float* w = conv ? w2 : w1;
    __half* dh = g_wh + (size_t)conv * 9 * 512 * 512;
    int ci0 = blockIdx.x * 32, co0 = blockIdx.y * 32;
    int tx = threadIdx.x & 31, ty = threadIdx.x >> 5;
#pragma unroll
    for (int r = 0; r < 4; ++r)
        tile[ty + r * 8][tx] = w[(((size_t)t * 512 + ci0 + ty + r * 8) << 9) + co0 + tx];
    __syncthreads();
#pragma unroll
    for (int r = 0; r < 4; ++r) {
        int co = co0 + ty + r * 8;
        dh[(((size_t)t * 512 + co) << 9) + ci0 + tx] = __float2half_rn(tile[tx][ty + r * 8]);
    }
}

// ---- HMMA implicit-GEMM conv: CTA 128px x 128cout, 8 warps (4M x 2N), K-stage 64 ----
struct TapList { int n; int dy[9]; int dx[9]; int wi[9]; };
#define ASTAGE 18432         // 128 rows * 144B
#define STAGE  36864         // A + B(128 rows * 144B)
#define SMEMSZ (3 * STAGE)   // 110592 -> 2 CTAs/SM

__global__ __launch_bounds__(256, 2)
void mma_conv_kernel(const __half* __restrict__ xin, int Hin, int Win,
                     const __half* __restrict__ wh,
                     TapList taps, int tilesPerImg, int pxs, int pxm,
                     int ymul, int yadd, int xmul, int xadd,
                     float* __restrict__ out,
                     const float* __restrict__ dvec, const float* __restrict__ noise,
                     const float* __restrict__ snoise, const float* __restrict__ bias) {
    extern __shared__ __align__(16) char smem[];
    const uint32_t su = smem_u32(smem);
    const int tid = threadIdx.x, lane = tid & 31, wid = tid >> 5;
    const int b = blockIdx.y / tilesPerImg;
    const int a0 = (blockIdx.y % tilesPerImg) * (128 >> pxs);
    const int cout0 = blockIdx.x * 128;
    const int m0 = (wid & 3) * 32, n0 = (wid >> 2) * 64;

    float acc[2][8][4];
#pragma unroll
    for (int i = 0; i < 2; ++i)
#pragma unroll
        for (int j = 0; j < 8; ++j)
#pragma unroll
            for (int k = 0; k < 4; ++k) acc[i][j][k] = 0.f;

    const int S = taps.n * 8;

    auto load_stage = [&](int st, int p) {
        int t = st >> 3, ck = (st & 7) << 6;
        uint32_t base = su + p * STAGE;
        int dy = taps.dy[t], dx = taps.dx[t];
#pragma unroll
        for (int i = 0; i < 4; ++i) {   // A: 128 rows x 64 fp16
            int id = tid + i * 256;
            int r = id >> 3, seg = id & 7;
            int iy = a0 + (r >> pxs) + dy, ix = (r & pxm) + dx;
            bool ok = ((unsigned)iy < (unsigned)Hin) && ((unsigned)ix < (unsigned)Win);
            const void* src = xin + ((((size_t)b * Hin + (ok ? iy : 0)) * Win + (ok ? ix : 0)) << 9)
                              + ck + (seg << 3);
            cpa16(base + r * 144 + seg * 16, src, ok ? 16u : 0u);
        }
        const __half* wt = wh + (((size_t)(taps.wi[t] * 512 + cout0)) << 9) + ck;
#pragma unroll
        for (int i = 0; i < 4; ++i) {   // B: 128 rows x 64 fp16
            int id = tid + i * 256;
            int row = id >> 3, seg = id & 7;
            cpa16(base + ASTAGE + row * 144 + seg * 16, wt + ((size_t)row << 9) + (seg << 3), 16u);
        }
    };

    auto compute = [&](int p) {
        uint32_t Ab = su + p * STAGE;
        uint32_t Bb = Ab + ASTAGE;
#pragma unroll
        for (int kk = 0; kk < 64; kk += 16) {
            uint32_t a[2][4];
#pragma unroll
            for (int mi = 0; mi < 2; ++mi) {
                uint32_t addr = Ab + (m0 + mi * 16 + (lane & 15)) * 144
                                + (kk + ((lane >> 4) << 3)) * 2;
                LDSM4(a[mi][0], a[mi][1], a[mi][2], a[mi][3], addr);
            }
            uint32_t bb[8][2];
#pragma unroll
            for (int ng = 0; ng < 4; ++ng) {
                int row = n0 + ng * 16 + (lane & 7) + ((lane >> 4) << 3);
                uint32_t addr = Bb + row * 144 + (kk + (((lane >> 3) & 1) << 3)) * 2;
                uint32_t r0, r1, r2, r3;
                LDSM4(r0, r1, r2, r3, addr);
                bb[ng * 2][0] = r0;     bb[ng * 2][1] = r1;
                bb[ng * 2 + 1][0] = r2; bb[ng * 2 + 1][1] = r3;
            }
#pragma unroll
            for (int mi = 0; mi < 2; ++mi)
#pragma unroll
                for (int ni = 0; ni < 8; ++ni)
                    mma16816(acc[mi][ni], a[mi], bb[ni]);
        }
    };

    load_stage(0, 0); CP_COMMIT();
    load_stage(1, 1); CP_COMMIT();
    for (int st = 0; st < S; ++st) {
        int nxt = st + 2;
        if (nxt < S) { load_stage(nxt, nxt % 3); CP_COMMIT(); CP_WAIT2(); }
        else if (st + 1 < S) { CP_WAIT1(); }
        else { CP_WAIT0(); }
        __syncthreads();
        compute(st % 3);
        __syncthreads();
    }

    // epilogue
    const int quad = lane >> 2, tq = lane & 3;
    if (dvec) {
        float2 dv2[8], sn2[8], bi2[8];
#pragma unroll
        for (int ni = 0; ni < 8; ++ni) {
            int col = cout0 + n0 + ni * 8 + tq * 2;
            dv2[ni] = *(const float2*)(dvec + b * 512 + col);
            sn2[ni] = *(const float2*)(snoise + col);
            bi2[ni] = *(const float2*)(bias + col);
        }
#pragma unroll
        for (int mi = 0; mi < 2; ++mi)
#pragma unroll
            for (int h = 0; h < 2; ++h) {
                int r = m0 + mi * 16 + quad + h * 8;
                int oy = (a0 + (r >> pxs)) * ymul + yadd;
                int ox = (r & pxm) * xmul + xadd;
                size_t pbase = (((size_t)b * 64 + oy) * 64 + ox) << 9;
                float nz = noise[(((size_t)b * 64 + oy) << 6) + ox];
#pragma unroll
                for (int ni = 0; ni < 8; ++ni) {
                    float c0 = acc[mi][ni][h * 2], c1 = acc[mi][ni][h * 2 + 1];
                    float2 v;
                    v.x = c0 * dv2[ni].x + sn2[ni].x * nz + bi2[ni].x;
                    v.y = c1 * dv2[ni].y + sn2[ni].y * nz + bi2[ni].y;
                    v.x = v.x >= 0.f ? v.x : 0.2f * v.x;
                    v.y = v.y >= 0.f ? v.y : 0.2f * v.y;
                    *(float2*)(out + pbase + cout0 + n0 + ni * 8 + tq * 2) = v;
                }
            }
    } else {
#pragma unroll
        for (int mi = 0; mi < 2; ++mi)
#pragma unroll
            for (int h = 0; h < 2; ++h) {
                int r = m0 + mi * 16 + quad + h * 8;
                int oy = (a0 + (r >> pxs)) * ymul + yadd;
                int ox = (r & pxm) * xmul + xadd;
                size_t pbase = (((size_t)b * 64 + oy) * 64 + ox) << 9;
#pragma unroll
                for (int ni = 0; ni < 8; ++ni) {
                    float2 v = make_float2(acc[mi][ni][h * 2], acc[mi][ni][h * 2 + 1]);
                    *(float2*)(out + pbase + cout0 + n0 + ni * 8 + tq * 2) = v;
                }
            }
    }
}

// ---- blur + demod1 + noise + bias + lrelu -> fp16 (v*s2*wscale) ----
__global__ void blur_kernel(const float* __restrict__ ydc, __half* __restrict__ xout,
                            const float* __restrict__ noise, const float* __restrict__ snoise,
                            const float* __restrict__ bias) {
    const int cg = threadIdx.x & 127, c = cg * 4;
    const int xi = (blockIdx.x % 32) * 2 + (threadIdx.x >> 7);
    const int b = blockIdx.x / 32;
    const float F[4] = {0.25f, 0.75f, 0.75f, 0.25f};

    float4 dvv = *(const float4*)(&g_d[0][b * 512 + c]);
    float4 snv = *(const float4*)(snoise + c);
    float4 biv = *(const float4*)(bias + c);
    float4 s2v = *(const float4*)(&g_s2[b * 512 + c]);

    auto hrow = [&](int v) -> float4 {
        float4 r = make_float4(0.f, 0.f, 0.f, 0.f);
        if (v < 0 || v >= 64) return r;
        const float* base = ydc + (((size_t)b * 64 + v) * 64) * 512 + c;
#pragma unroll
        for (int u = 0; u < 4; ++u) {
            int xx = xi + u - 1;
            if (xx >= 0 && xx < 64) {
                float4 t = *(const float4*)(base + (size_t)xx * 512);
                r.x += F[u] * t.x; r.y += F[u] * t.y; r.z += F[u] * t.z; r.w += F[u] * t.w;
            }
        }
        return r;
    };

    float4 h0 = make_float4(0.f, 0.f, 0.f, 0.f);
    float4 h1 = hrow(0), h2 = hrow(1);
    for (int y = 0; y < 64; ++y) {
        float4 h3 = hrow(y + 2);
        float4 o;
        o.x = 0.25f * h0.x + 0.75f * h1.x + 0.75f * h2.x + 0.25f * h3.x;
        o.y = 0.25f * h0.y + 0.75f * h1.y + 0.75f * h2.y + 0.25f * h3.y;
        o.z = 0.25f * h0.z + 0.75f * h1.z + 0.75f * h2.z + 0.25f * h3.z;
        o.w = 0.25f * h0.w + 0.75f * h1.w + 0.75f * h2.w + 0.25f * h3.w;
        float nz = noise[((size_t)b * 64 + y) * 64 + xi];
        float4 v;
        v.x = o.x * dvv.x + snv.x * nz + biv.x;
        v.y = o.y * dvv.y + snv.y * nz + biv.y;
        v.z = o.z * dvv.z + snv.z * nz + biv.z;
        v.w = o.w * dvv.w + snv.w * nz + biv.w;
        v.x = v.x >= 0.f ? v.x : 0.2f * v.x;
        v.y = v.y >= 0.f ? v.y : 0.2f * v.y;
        v.z = v.z >= 0.f ? v.z : 0.2f * v.z;
        v.w = v.w >= 0.f ? v.w : 0.2f * v.w;
        size_t off = (((size_t)b * 64 + y) * 64 + xi) * 512 + c;
        __half2 p0 = __floats2half2_rn(v.x * s2v.x * WS9F, v.y * s2v.y * WS9F);
        __half2 p1 = __floats2half2_rn(v.z * s2v.z * WS9F, v.w * s2v.w * WS9F);
        ((__half2*)(xout + off))[0] = p0;
        ((__half2*)(xout + off))[1] = p1;
        h0 = h1; h1 = h2; h2 = h3;
    }
}

// ---- toRGB ----
__global__ void torgb_kernel(const float* __restrict__ x2, float* __restrict__ rgb,
                             const float* __restrict__ biasr) {
    const int warp = threadIdx.x >> 5, lane = threadIdx.x & 31;
    const int pix = blockIdx.x * 8 + warp;
    const int b = pix >> 12;
    const float* xp = x2 + (size_t)pix * 512;
    const float* sp = g_sr + b * 512;
    float r0 = 0.f, r1 = 0.f, r2 = 0.f;
#pragma unroll
    for (int k = 0; k < 4; ++k) {
        int c = lane * 4 + k * 128;
        float4 xv = *(const float4*)(xp + c);
        float4 sv = *(const float4*)(sp + c);
        xv.x *= sv.x; xv.y *= sv.y; xv.z *= sv.z; xv.w *= sv.w;
        float4 w0 = *(const float4*)(g_wr3 + 0 * 512 + c);
        float4 w1 = *(const float4*)(g_wr3 + 1 * 512 + c);
        float4 w2 = *(const float4*)(g_wr3 + 2 * 512 + c);
        r0 += xv.x * w0.x + xv.y * w0.y + xv.z * w0.z + xv.w * w0.w;
        r1 += xv.x * w1.x + xv.y * w1.y + xv.z * w1.z + xv.w * w1.w;
        r2 += xv.x * w2.x + xv.y * w2.y + xv.z * w2.z + xv.w * w2.w;
    }
#pragma unroll
    for (int off = 16; off > 0; off >>= 1) {
        r0 += __shfl_xor_sync(0xffffffffu, r0, off);
        r1 += __shfl_xor_sync(0xffffffffu, r1, off);
        r2 += __shfl_xor_sync(0xffffffffu, r2, off);
    }
    if (lane == 0) {
        float v0 = r0 + biasr[0], v1 = r1 + biasr[1], v2 = r2 + biasr[2];
        rgb[(size_t)pix * 3 + 0] = v0 >= 0.f ? v0 : 0.2f * v0;
        rgb[(size_t)pix * 3 + 1] = v1 >= 0.f ? v1 : 0.2f * v1;
        rgb[(size_t)pix * 3 + 2] = v2 >= 0.f ? v2 : 0.2f * v2;
    }
}

// ---- launch ----
extern "C" void kernel_launch(void* const* d_in, const int* in_sizes, int n_in,
                              void* d_out, int out_size) {
    const float* x       = (const float*)d_in[0];
    const float* w       = (const float*)d_in[1];
    const float* noise1  = (const float*)d_in[2];
    const float* noise2  = (const float*)d_in[3];
    const float* fcl1_w  = (const float*)d_in[4];
    const float* fcl1_b  = (const float*)d_in[5];
    const float* conv1_w = (const float*)d_in[6];
    const float* sn1     = (const float*)d_in[7];
    const float* bias1   = (const float*)d_in[8];
    const float* fcl2_w  = (const float*)d_in[9];
    const float* fcl2_b  = (const float*)d_in[10];
    const float* conv2_w = (const float*)d_in[11];
    const float* sn2     = (const float*)d_in[12];
    const float* bias2   = (const float*)d_in[13];
    const float* fclr_w  = (const float*)d_in[14];
    const float* fclr_b  = (const float*)d_in[15];
    const float* convr_w = (const float*)d_in[16];
    const float* biasr   = (const float*)d_in[17];

    float* x2out  = (float*)d_out;
    float* rgbout = x2out + (size_t)B_ * 64 * 64 * 512;

    float *s1, *s2, *sr, *dd, *ydc;
    __half *a1, *a2, *wh;
    cudaGetSymbolAddress((void**)&s1, g_s1);
    cudaGetSymbolAddress((void**)&s2, g_s2);
    cudaGetSymbolAddress((void**)&sr, g_sr);
    cudaGetSymbolAddress((void**)&dd, g_d);
    cudaGetSymbolAddress((void**)&ydc, g_ydc);
    cudaGetSymbolAddress((void**)&a1, g_a1);
    cudaGetSymbolAddress((void**)&a2, g_a2);
    cudaGetSymbolAddress((void**)&wh, g_wh);
    float* d2 = dd + B_ * 512;

    cudaFuncSetAttribute(mma_conv_kernel, cudaFuncAttributeMaxDynamicSharedMemorySize, SMEMSZ);

    fcl_kernel<<<B_, 512>>>(w, fcl1_w, fcl1_b, s1);
    fcl_kernel<<<B_, 512>>>(w, fcl2_w, fcl2_b, s2);
    fcl_kernel<<<B_, 512>>>(w, fclr_w, fclr_b, sr);
    a_kernel<<<dim3(512, 2), 512>>>(conv1_w, conv2_w);
    d_kernel<<<dim3(B_, 2), 512>>>();
    wr3_kernel<<<1, 512>>>(convr_w);
    prep_a1<<<8192, 256>>>(x);
    wprep_kernel<<<dim3(16, 16, 18), 256>>>(conv1_w, conv2_w);

    // deconv: 4 parity classes (dense shifted GEMMs), 128-px tiles (4 rows x 32)
    for (int rh = 0; rh < 2; ++rh) {
        for (int rw = 0; rw < 2; ++rw) {
            TapList tl;
            int n = 0;
            const int khs0[2] = {0, 2};
            int nkh = rh ? 1 : 2, nkw = rw ? 1 : 2;
            for (int ih = 0; ih < nkh; ++ih) {
                int kh = rh ? 1 : khs0[ih];
                for (int iw = 0; iw < nkw; ++iw) {
                    int kw = rw ? 1 : khs0[iw];
                    tl.dy[n] = (kh == 0) ? -1 : 0;
                    tl.dx[n] = (kw == 0) ? -1 : 0;
                    tl.wi[n] = kh * 3 + kw;
                    ++n;
                }
            }
            tl.n = n;
            mma_conv_kernel<<<dim3(4, B_ * 8), 256, SMEMSZ>>>(
                a1, 32, 32, wh, tl, 8, 5, 31,
                2, rh, 2, rw, ydc, nullptr, nullptr, nullptr, nullptr);
        }
    }

    blur_kernel<<<B_ * 32, 256>>>(ydc, a2, noise1, sn1, bias1);

    // conv2: 3x3 SAME, fused demod/noise/bias/lrelu -> d_out (128-px tiles: 2 rows x 64)
    {
        TapList tl;
        tl.n = 9;
        for (int kh = 0; kh < 3; ++kh)
            for (int kw = 0; kw < 3; ++kw) {
                int t = kh * 3 + kw;
                tl.dy[t] = kh - 1; tl.dx[t] = kw - 1; tl.wi[t] = t;
            }
        mma_conv_kernel<<<dim3(4, B_ * 32), 256, SMEMSZ>>>(
            a2, 64, 64, wh + (size_t)9 * 512 * 512, tl, 32, 6, 63,
            1, 0, 1, 0, x2out, d2, noise2, sn2, bias2);
    }

    torgb_kernel<<<(B_ * 64 * 64) / 8, 256>>>(x2out, rgbout, biasr);
}